// round 1
// baseline (speedup 1.0000x reference)
#include <cuda_runtime.h>
#include <math.h>
#include <stdint.h>

#define NDET 512
#define NC   81
#define HW   784
#define KPAD 800
#define NMS_THRESH 0.5
#define EPSV 1e-4

// ---------------- scratch (static device memory; no runtime allocation) ----
__device__ double        g_Pd[2][NDET][KPAD];     // sorted, zero-padded probs (f64)
__device__ double        g_ud[2][NDET];           // sorted row sums (f64, ~exact)
__device__ unsigned char g_mask[2][NDET][NDET];   // mask[i][j] = iou(i,j) >= thresh
__device__ unsigned char g_sup[2][NDET];          // suppression flags (sorted order)
__device__ int           g_order[NDET];           // order[r] = original index
__device__ int           g_rank[NDET];            // rank[n]  = sorted position

// ---------------- 1. stable argsort(-scores) via O(N^2) rank ---------------
__global__ void order_kernel(const float* __restrict__ scores) {
    int i = threadIdx.x;
    float si = scores[i];
    int r = 0;
#pragma unroll 8
    for (int j = 0; j < NDET; ++j) {
        float sj = __ldg(&scores[j]);
        r += (sj > si) || (sj == si && j < i);
    }
    g_rank[i] = r;
    g_order[r] = i;
}

// ---------------- 2. gather channel, sigmoid, write probs + sorted f64 P ---
__global__ void prob_kernel(const float* __restrict__ left,
                            const float* __restrict__ right,
                            const int*   __restrict__ labels,
                            float*       __restrict__ out) {
    int b = blockIdx.x;
    int side = b >> 9;
    int n = b & (NDET - 1);
    const float* base = side ? right : left;
    int c = labels[n];
    const float* row = base + ((size_t)n * NC + c) * HW;
    float* orow = out + ((size_t)side * NDET + n) * HW;
    int r = g_rank[n];
    double* prow = g_Pd[side][r];

    double s = 0.0;
    for (int k = threadIdx.x; k < HW; k += blockDim.x) {
        float x = row[k];
        float p = 1.0f / (1.0f + expf(-x));
        orow[k] = p;
        prow[k] = (double)p;
        s += (double)p;
    }
    for (int k = HW + threadIdx.x; k < KPAD; k += blockDim.x) prow[k] = 0.0;

    // block reduce (f64)
    __shared__ double red[8];
    for (int o = 16; o; o >>= 1) s += __shfl_down_sync(0xffffffffu, s, o);
    if ((threadIdx.x & 31) == 0) red[threadIdx.x >> 5] = s;
    __syncthreads();
    if (threadIdx.x == 0) {
        double t = 0.0;
#pragma unroll
        for (int w = 0; w < 8; ++w) t += red[w];
        g_ud[side][r] = t;
    }
}

// ---------------- 3. f64 Gram (P P^T) + IoU threshold -> byte mask ---------
// BM=BN=64, BK=16, 256 threads, 4x4 micro-tile per thread.
__global__ void gemm_mask_kernel() {
    int side = blockIdx.z;
    __shared__ double As[16][65];
    __shared__ double Bs[16][65];
    int tid = threadIdx.x;
    int tx = tid & 15, ty = tid >> 4;
    int arow0 = blockIdx.y * 64;
    int brow0 = blockIdx.x * 64;
    const double* P = &g_Pd[side][0][0];

    double acc[4][4];
#pragma unroll
    for (int m = 0; m < 4; ++m)
#pragma unroll
        for (int n = 0; n < 4; ++n) acc[m][n] = 0.0;

    for (int kt = 0; kt < KPAD; kt += 16) {
#pragma unroll
        for (int l = tid; l < 64 * 16; l += 256) {
            int rr = l >> 4, cc = l & 15;
            As[cc][rr] = P[(size_t)(arow0 + rr) * KPAD + kt + cc];
            Bs[cc][rr] = P[(size_t)(brow0 + rr) * KPAD + kt + cc];
        }
        __syncthreads();
#pragma unroll
        for (int kk = 0; kk < 16; ++kk) {
            double a[4], bb[4];
#pragma unroll
            for (int m = 0; m < 4; ++m) a[m] = As[kk][ty * 4 + m];
#pragma unroll
            for (int n = 0; n < 4; ++n) bb[n] = Bs[kk][tx * 4 + n];
#pragma unroll
            for (int m = 0; m < 4; ++m)
#pragma unroll
                for (int n = 0; n < 4; ++n) acc[m][n] = fma(a[m], bb[n], acc[m][n]);
        }
        __syncthreads();
    }

#pragma unroll
    for (int m = 0; m < 4; ++m) {
        int gi = arow0 + ty * 4 + m;
        double den = g_ud[side][gi] + EPSV;
#pragma unroll
        for (int n = 0; n < 4; ++n) {
            int gj = brow0 + tx * 4 + n;
            g_mask[side][gi][gj] = (acc[m][n] / den >= NMS_THRESH) ? 1 : 0;
        }
    }
}

// ---------------- 4. greedy sequential suppression (bit-packed in smem) ----
__global__ void nms_kernel() {
    int side = blockIdx.x;
    int j = threadIdx.x;  // 512 threads
    __shared__ unsigned int  bits[NDET * 16];  // 512 rows x 512 bits = 32KB
    __shared__ unsigned char sup[NDET];

    for (int w = threadIdx.x; w < NDET * 16; w += blockDim.x) {
        int i = w >> 4, ww = w & 15;
        const uchar4* p = (const uchar4*)&g_mask[side][i][ww * 32];
        unsigned int v = 0;
#pragma unroll
        for (int q = 0; q < 8; ++q) {
            uchar4 u4 = p[q];
            v |= (u4.x ? 1u : 0u) << (q * 4 + 0);
            v |= (u4.y ? 1u : 0u) << (q * 4 + 1);
            v |= (u4.z ? 1u : 0u) << (q * 4 + 2);
            v |= (u4.w ? 1u : 0u) << (q * 4 + 3);
        }
        bits[w] = v;
    }
    sup[j] = 0;
    __syncthreads();

    int wsel = j >> 5;
    unsigned int mybit = 1u << (j & 31);
    for (int i = 0; i < NDET; ++i) {
        // sup[i] is final before iteration i (writers always target j > i)
        if (!sup[i] && j > i && (bits[i * 16 + wsel] & mybit)) sup[j] = 1;
        __syncthreads();
    }
    g_sup[side][j] = sup[j];
}

// ---------------- 5. keep[order[r]] = valid & !supL & !supR ----------------
__global__ void finalize_kernel(float* __restrict__ out, int out_size) {
    int r = threadIdx.x;
    int n = g_order[r];
    bool valid = (g_ud[0][r] > 0.0) && (g_ud[1][r] > 0.0);
    float k = (valid && !g_sup[0][r] && !g_sup[1][r]) ? 1.0f : 0.0f;
    if (out_size >= 2 * NDET * HW + NDET)
        out[2 * NDET * HW + n] = k;
}

// ---------------- launch ----------------------------------------------------
extern "C" void kernel_launch(void* const* d_in, const int* in_sizes, int n_in,
                              void* d_out, int out_size) {
    const float* left   = (const float*)d_in[0];
    const float* right  = (const float*)d_in[1];
    const float* scores = (const float*)d_in[2];
    const int*   labels = (const int*)d_in[3];
    float* out = (float*)d_out;
    (void)in_sizes; (void)n_in;

    order_kernel<<<1, NDET>>>(scores);
    prob_kernel<<<2 * NDET, 256>>>(left, right, labels, out);
    dim3 ggrid(8, 8, 2);
    gemm_mask_kernel<<<ggrid, 256>>>();
    nms_kernel<<<2, NDET>>>();
    finalize_kernel<<<1, NDET>>>(out, out_size);
}

// round 2
// speedup vs baseline: 3.9826x; 3.9826x over previous
#include <cuda_runtime.h>
#include <math.h>
#include <stdint.h>

#define NDET 512
#define NC   81
#define HW   784
#define NMS_THRESH 0.5
#define EPSV 1e-4
#define TAU  2e-4f
#define FLAG_CAP (1 << 18)

// ---------------- scratch (static device memory) ----------------------------
__device__ __align__(16) float  g_Pf[2][NDET][HW];   // sorted probs (f32)
__device__ double        g_ud[2][NDET];              // sorted row sums (f64)
__device__ unsigned int  g_bits[2][NDET][16];        // bit-packed mask rows
__device__ unsigned char g_sup[2][NDET];             // suppression (sorted order)
__device__ int           g_order[NDET];
__device__ int           g_rank[NDET];
__device__ int           g_nflag;
__device__ int           g_flags[FLAG_CAP];          // packed (side<<20)|(i<<10)|j

// ---------------- 1. stable argsort(-scores) + state reset ------------------
__global__ void order_kernel(const float* __restrict__ scores) {
    int i = threadIdx.x;
    float si = scores[i];
    int r = 0;
#pragma unroll 8
    for (int j = 0; j < NDET; ++j) {
        float sj = __ldg(&scores[j]);
        r += (sj > si) || (sj == si && j < i);
    }
    g_rank[i] = r;
    g_order[r] = i;
    if (i == 0) g_nflag = 0;
    unsigned int* bz = &g_bits[0][0][0];
#pragma unroll
    for (int w = 0; w < 32; ++w) bz[i + w * NDET] = 0u;   // 2*512*16 = 16384 words
}

// ---------------- 2. gather channel, sigmoid, write probs + sorted f32 P ----
__global__ void prob_kernel(const float* __restrict__ left,
                            const float* __restrict__ right,
                            const int*   __restrict__ labels,
                            float*       __restrict__ out) {
    int b = blockIdx.x;
    int side = b >> 9;
    int n = b & (NDET - 1);
    const float* base = side ? right : left;
    int c = labels[n];
    const float* row = base + ((size_t)n * NC + c) * HW;
    float* orow = out + ((size_t)side * NDET + n) * HW;
    int r = g_rank[n];
    float* prow = g_Pf[side][r];

    double s = 0.0;
    for (int k = threadIdx.x; k < HW; k += blockDim.x) {
        float x = row[k];
        float p = 1.0f / (1.0f + expf(-x));
        orow[k] = p;
        prow[k] = p;
        s += (double)p;
    }
    __shared__ double red[8];
    for (int o = 16; o; o >>= 1) s += __shfl_down_sync(0xffffffffu, s, o);
    if ((threadIdx.x & 31) == 0) red[threadIdx.x >> 5] = s;
    __syncthreads();
    if (threadIdx.x == 0) {
        double t = 0.0;
#pragma unroll
        for (int w = 0; w < 8; ++w) t += red[w];
        g_ud[side][r] = t;
    }
}

// ---------------- 3. f32 Gram + threshold -> packed bits + flag list --------
// BM=BN=64, BK=16, 256 threads, 4x4 micro-tile. Near-threshold pairs flagged.
__global__ void gemm_mask_kernel() {
    int side = blockIdx.z;
    __shared__ __align__(16) float As[16][68];
    __shared__ __align__(16) float Bs[16][68];
    __shared__ unsigned int sbits[64][2];
    int tid = threadIdx.x;
    int tx = tid & 15, ty = tid >> 4;
    int arow0 = blockIdx.y * 64;
    int brow0 = blockIdx.x * 64;
    const float* P = &g_Pf[side][0][0];

    float acc[4][4];
#pragma unroll
    for (int m = 0; m < 4; ++m)
#pragma unroll
        for (int n = 0; n < 4; ++n) acc[m][n] = 0.0f;

    int rr = tid >> 2, kq = (tid & 3) * 4;
    for (int kt = 0; kt < HW; kt += 16) {
        float4 av = *(const float4*)&P[(size_t)(arow0 + rr) * HW + kt + kq];
        float4 bv = *(const float4*)&P[(size_t)(brow0 + rr) * HW + kt + kq];
        As[kq + 0][rr] = av.x; As[kq + 1][rr] = av.y;
        As[kq + 2][rr] = av.z; As[kq + 3][rr] = av.w;
        Bs[kq + 0][rr] = bv.x; Bs[kq + 1][rr] = bv.y;
        Bs[kq + 2][rr] = bv.z; Bs[kq + 3][rr] = bv.w;
        __syncthreads();
#pragma unroll
        for (int kk = 0; kk < 16; ++kk) {
            float4 a4 = *(const float4*)&As[kk][ty * 4];
            float4 b4 = *(const float4*)&Bs[kk][tx * 4];
            float a[4] = {a4.x, a4.y, a4.z, a4.w};
            float bb[4] = {b4.x, b4.y, b4.z, b4.w};
#pragma unroll
            for (int m = 0; m < 4; ++m)
#pragma unroll
                for (int n = 0; n < 4; ++n) acc[m][n] = fmaf(a[m], bb[n], acc[m][n]);
        }
        __syncthreads();
    }

    if (tid < 128) ((unsigned int*)sbits)[tid] = 0u;
    __syncthreads();

#pragma unroll
    for (int m = 0; m < 4; ++m) {
        int li = ty * 4 + m;            // row in tile
        int gi = arow0 + li;
        float den = (float)(g_ud[side][gi] + EPSV);
        unsigned int nib = 0;
#pragma unroll
        for (int n = 0; n < 4; ++n) {
            float mg = acc[m][n] - 0.5f * den;
            if (mg >= 0.0f) nib |= (1u << n);
            if (fabsf(mg) <= TAU * den) {
                int gj = brow0 + tx * 4 + n;
                int idx = atomicAdd(&g_nflag, 1);
                if (idx < FLAG_CAP)
                    g_flags[idx] = (side << 20) | (gi << 10) | gj;
            }
        }
        atomicOr(&sbits[li][tx >> 3], nib << ((tx & 7) * 4));
    }
    __syncthreads();
    if (tid < 128) {
        int r = tid >> 1, w = tid & 1;
        g_bits[side][arow0 + r][(brow0 >> 5) + w] = sbits[r][w];
    }
}

// ---------------- 3b. f64 refinement of near-threshold pairs ----------------
__global__ void refine_kernel() {
    int lane = threadIdx.x & 31;
    int warp = (blockIdx.x * blockDim.x + threadIdx.x) >> 5;
    int nwarps = (gridDim.x * blockDim.x) >> 5;
    int n = g_nflag;
    if (n > FLAG_CAP) n = FLAG_CAP;
    for (int p = warp; p < n; p += nwarps) {
        int v = g_flags[p];
        int side = v >> 20, i = (v >> 10) & 1023, j = v & 1023;
        const float* Pi = g_Pf[side][i];
        const float* Pj = g_Pf[side][j];
        double s = 0.0;
        for (int k = lane; k < HW; k += 32)
            s += (double)Pi[k] * (double)Pj[k];
        for (int o = 16; o; o >>= 1) s += __shfl_down_sync(0xffffffffu, s, o);
        if (lane == 0) {
            double den = g_ud[side][i] + EPSV;
            unsigned int bit = 1u << (j & 31);
            unsigned int* w = &g_bits[side][i][j >> 5];
            if (s / den >= NMS_THRESH) atomicOr(w, bit);
            else                       atomicAnd(w, ~bit);
        }
    }
}

// ---------------- 4. greedy suppression: single warp, register bitset -------
__global__ void nms_kernel() {
    int side = blockIdx.x;
    __shared__ unsigned int rb[NDET * 16];
    int lane = threadIdx.x;  // 32 threads
    const uint4* src = (const uint4*)&g_bits[side][0][0];
    for (int q = lane; q < NDET * 4; q += 32) ((uint4*)rb)[q] = src[q];
    __syncwarp();

    unsigned int removed = 0;  // lane w<16 holds suppression word w
    for (int i = 0; i < NDET; ++i) {
        int rw = i >> 5, rbit = i & 31;
        unsigned int supw = __shfl_sync(0xffffffffu, removed, rw);
        if (!((supw >> rbit) & 1u)) {
            unsigned int m = (lane < 16) ? rb[i * 16 + lane] : 0u;
            if (lane < rw) m = 0u;
            else if (lane == rw)
                m &= (rbit == 31) ? 0u : (0xFFFFFFFFu << (rbit + 1));
            removed |= m;
        }
    }
    if (lane < 16) {
#pragma unroll
        for (int b = 0; b < 32; ++b)
            g_sup[side][lane * 32 + b] = (removed >> b) & 1u;
    }
}

// ---------------- 5. keep[order[r]] = valid & !supL & !supR -----------------
__global__ void finalize_kernel(float* __restrict__ out, int out_size) {
    int r = threadIdx.x;
    int n = g_order[r];
    bool valid = (g_ud[0][r] > 0.0) && (g_ud[1][r] > 0.0);
    float k = (valid && !g_sup[0][r] && !g_sup[1][r]) ? 1.0f : 0.0f;
    if (out_size >= 2 * NDET * HW + NDET)
        out[2 * NDET * HW + n] = k;
}

// ---------------- launch -----------------------------------------------------
extern "C" void kernel_launch(void* const* d_in, const int* in_sizes, int n_in,
                              void* d_out, int out_size) {
    const float* left   = (const float*)d_in[0];
    const float* right  = (const float*)d_in[1];
    const float* scores = (const float*)d_in[2];
    const int*   labels = (const int*)d_in[3];
    float* out = (float*)d_out;
    (void)in_sizes; (void)n_in;

    order_kernel<<<1, NDET>>>(scores);
    prob_kernel<<<2 * NDET, 256>>>(left, right, labels, out);
    dim3 ggrid(8, 8, 2);
    gemm_mask_kernel<<<ggrid, 256>>>();
    refine_kernel<<<64, 256>>>();
    nms_kernel<<<2, 32>>>();
    finalize_kernel<<<1, NDET>>>(out, out_size);
}

// round 3
// speedup vs baseline: 4.3697x; 1.0972x over previous
#include <cuda_runtime.h>
#include <math.h>
#include <stdint.h>

#define NDET 512
#define NC   81
#define HW   784
#define NMS_THRESH 0.5
#define EPSV 1e-4
#define TAU  2e-6          // iou-units flag margin; worst-case f32 err <= 4.8e-7
#define FLAG_CAP (1 << 16)

// ---------------- scratch (static device memory) ----------------------------
__device__ __align__(16) float  g_Pf[2][NDET][HW];   // sorted probs (f32)
__device__ double        g_ud[2][NDET];              // sorted row sums (f64)
__device__ __align__(16) unsigned int g_bits[2][NDET][16]; // packed mask rows
__device__ unsigned char g_sup[2][NDET];             // suppression (sorted order)
__device__ int           g_order[NDET];
__device__ int           g_rank[NDET];
__device__ int           g_nflag;
__device__ int           g_flags[FLAG_CAP];          // packed (side<<20)|(i<<10)|j

// ---------------- 1. stable argsort(-scores) --------------------------------
__global__ void order_kernel(const float* __restrict__ scores) {
    int i = threadIdx.x;
    float si = scores[i];
    int r = 0;
#pragma unroll 8
    for (int j = 0; j < NDET; ++j) {
        float sj = __ldg(&scores[j]);
        r += (sj > si) || (sj == si && j < i);
    }
    g_rank[i] = r;
    g_order[r] = i;
    if (i == 0) g_nflag = 0;
}

// ---------------- 2. gather channel, sigmoid, write probs + sorted f32 P ----
__global__ void prob_kernel(const float* __restrict__ left,
                            const float* __restrict__ right,
                            const int*   __restrict__ labels,
                            float*       __restrict__ out) {
    int b = blockIdx.x;
    int side = b >> 9;
    int n = b & (NDET - 1);
    const float* base = side ? right : left;
    int c = labels[n];
    const float* row = base + ((size_t)n * NC + c) * HW;
    float* orow = out + ((size_t)side * NDET + n) * HW;
    int r = g_rank[n];
    float* prow = g_Pf[side][r];

    double s = 0.0;
    for (int k = threadIdx.x; k < HW; k += blockDim.x) {
        float x = row[k];
        float p = 1.0f / (1.0f + expf(-x));
        orow[k] = p;
        prow[k] = p;
        s += (double)p;
    }
    __shared__ double red[8];
    for (int o = 16; o; o >>= 1) s += __shfl_down_sync(0xffffffffu, s, o);
    if ((threadIdx.x & 31) == 0) red[threadIdx.x >> 5] = s;
    __syncthreads();
    if (threadIdx.x == 0) {
        double t = 0.0;
#pragma unroll
        for (int w = 0; w < 8; ++w) t += red[w];
        g_ud[side][r] = t;
    }
}

// ---------------- 3. f32-tile/f64-total Gram + threshold -> packed bits -----
// BM=BN=64, BK=16, 256 threads, 4x4 micro-tile. Upper-triangular tiles only.
// Per-16k tile sums in f32, accumulated into f64 => worst-case iou err 4.8e-7.
__global__ void gemm_mask_kernel() {
    if (blockIdx.x < blockIdx.y) return;   // j-tiles >= i-tiles only
    int side = blockIdx.z;
    __shared__ __align__(16) float As[16][68];
    __shared__ __align__(16) float Bs[16][68];
    __shared__ unsigned int sbits[64][2];
    int tid = threadIdx.x;
    int tx = tid & 15, ty = tid >> 4;
    int arow0 = blockIdx.y * 64;
    int brow0 = blockIdx.x * 64;
    const float* P = &g_Pf[side][0][0];

    double acc[4][4];
#pragma unroll
    for (int m = 0; m < 4; ++m)
#pragma unroll
        for (int n = 0; n < 4; ++n) acc[m][n] = 0.0;

    int rr = tid >> 2, kq = (tid & 3) * 4;
    for (int kt = 0; kt < HW; kt += 16) {
        float4 av = *(const float4*)&P[(size_t)(arow0 + rr) * HW + kt + kq];
        float4 bv = *(const float4*)&P[(size_t)(brow0 + rr) * HW + kt + kq];
        As[kq + 0][rr] = av.x; As[kq + 1][rr] = av.y;
        As[kq + 2][rr] = av.z; As[kq + 3][rr] = av.w;
        Bs[kq + 0][rr] = bv.x; Bs[kq + 1][rr] = bv.y;
        Bs[kq + 2][rr] = bv.z; Bs[kq + 3][rr] = bv.w;
        __syncthreads();
        float tacc[4][4];
#pragma unroll
        for (int m = 0; m < 4; ++m)
#pragma unroll
            for (int n = 0; n < 4; ++n) tacc[m][n] = 0.0f;
#pragma unroll
        for (int kk = 0; kk < 16; ++kk) {
            float4 a4 = *(const float4*)&As[kk][ty * 4];
            float4 b4 = *(const float4*)&Bs[kk][tx * 4];
            float a[4] = {a4.x, a4.y, a4.z, a4.w};
            float bb[4] = {b4.x, b4.y, b4.z, b4.w};
#pragma unroll
            for (int m = 0; m < 4; ++m)
#pragma unroll
                for (int n = 0; n < 4; ++n) tacc[m][n] = fmaf(a[m], bb[n], tacc[m][n]);
        }
#pragma unroll
        for (int m = 0; m < 4; ++m)
#pragma unroll
            for (int n = 0; n < 4; ++n) acc[m][n] += (double)tacc[m][n];
        __syncthreads();
    }

    if (tid < 128) ((unsigned int*)sbits)[tid] = 0u;
    __syncthreads();

#pragma unroll
    for (int m = 0; m < 4; ++m) {
        int li = ty * 4 + m;
        int gi = arow0 + li;
        double den = g_ud[side][gi] + EPSV;
        unsigned int nib = 0;
#pragma unroll
        for (int n = 0; n < 4; ++n) {
            double mg = acc[m][n] - 0.5 * den;
            if (mg >= 0.0) nib |= (1u << n);
            if (fabs(mg) <= TAU * den) {
                int gj = brow0 + tx * 4 + n;
                int idx = atomicAdd(&g_nflag, 1);
                if (idx < FLAG_CAP)
                    g_flags[idx] = (side << 20) | (gi << 10) | gj;
            }
        }
        atomicOr(&sbits[li][tx >> 3], nib << ((tx & 7) * 4));
    }
    __syncthreads();
    if (tid < 128) {
        int r = tid >> 1, w = tid & 1;
        g_bits[side][arow0 + r][(brow0 >> 5) + w] = sbits[r][w];
    }
}

// ---------------- 3b. exact f64 refinement of near-threshold pairs ----------
__global__ void refine_kernel() {
    int lane = threadIdx.x & 31;
    int warp = (blockIdx.x * blockDim.x + threadIdx.x) >> 5;
    int nwarps = (gridDim.x * blockDim.x) >> 5;
    int n = g_nflag;
    if (n > FLAG_CAP) n = FLAG_CAP;
    for (int p = warp; p < n; p += nwarps) {
        int v = g_flags[p];
        int side = v >> 20, i = (v >> 10) & 1023, j = v & 1023;
        const float* Pi = g_Pf[side][i];
        const float* Pj = g_Pf[side][j];
        double s = 0.0;
#pragma unroll
        for (int q = 0; q < 25; ++q) {
            int k = lane + q * 32;
            float a = (k < HW) ? Pi[k] : 0.0f;
            float b = (k < HW) ? Pj[k] : 0.0f;
            s = fma((double)a, (double)b, s);
        }
        for (int o = 16; o; o >>= 1) s += __shfl_down_sync(0xffffffffu, s, o);
        if (lane == 0) {
            double den = g_ud[side][i] + EPSV;
            unsigned int bit = 1u << (j & 31);
            unsigned int* w = &g_bits[side][i][j >> 5];
            if (s / den >= NMS_THRESH) atomicOr(w, bit);
            else                       atomicAnd(w, ~bit);
        }
    }
}

// ---------------- 4. greedy suppression: single warp, register bitset -------
__global__ void nms_kernel() {
    int side = blockIdx.x;
    __shared__ unsigned int rb[NDET * 16];
    int lane = threadIdx.x;  // 32 threads
    const uint4* src = (const uint4*)&g_bits[side][0][0];
    for (int q = lane; q < NDET * 4; q += 32) ((uint4*)rb)[q] = src[q];
    __syncwarp();

    unsigned int removed = 0;  // lane w<16 holds suppression word w
    for (int i = 0; i < NDET; ++i) {
        int rw = i >> 5, rbit = i & 31;
        unsigned int supw = __shfl_sync(0xffffffffu, removed, rw);
        if (!((supw >> rbit) & 1u)) {
            unsigned int m = (lane < 16) ? rb[i * 16 + lane] : 0u;
            if (lane < rw) m = 0u;
            else if (lane == rw)
                m &= (rbit == 31) ? 0u : (0xFFFFFFFFu << (rbit + 1));
            removed |= m;
        }
    }
    if (lane < 16) {
#pragma unroll
        for (int b = 0; b < 32; ++b)
            g_sup[side][lane * 32 + b] = (removed >> b) & 1u;
    }
}

// ---------------- 5. keep[order[r]] = valid & !supL & !supR -----------------
__global__ void finalize_kernel(float* __restrict__ out, int out_size) {
    int r = threadIdx.x;
    int n = g_order[r];
    bool valid = (g_ud[0][r] > 0.0) && (g_ud[1][r] > 0.0);
    float k = (valid && !g_sup[0][r] && !g_sup[1][r]) ? 1.0f : 0.0f;
    if (out_size >= 2 * NDET * HW + NDET)
        out[2 * NDET * HW + n] = k;
}

// ---------------- launch -----------------------------------------------------
extern "C" void kernel_launch(void* const* d_in, const int* in_sizes, int n_in,
                              void* d_out, int out_size) {
    const float* left   = (const float*)d_in[0];
    const float* right  = (const float*)d_in[1];
    const float* scores = (const float*)d_in[2];
    const int*   labels = (const int*)d_in[3];
    float* out = (float*)d_out;
    (void)in_sizes; (void)n_in;

    order_kernel<<<1, NDET>>>(scores);
    prob_kernel<<<2 * NDET, 256>>>(left, right, labels, out);
    dim3 ggrid(8, 8, 2);
    gemm_mask_kernel<<<ggrid, 256>>>();
    refine_kernel<<<64, 256>>>();
    nms_kernel<<<2, 32>>>();
    finalize_kernel<<<1, NDET>>>(out, out_size);
}

// round 4
// speedup vs baseline: 9.5488x; 2.1852x over previous
#include <cuda_runtime.h>
#include <math.h>
#include <stdint.h>

#define NDET 512
#define NC   81
#define HW   784
#define NMS_THRESH 0.5
#define EPSV 1e-4
#define TAU  4e-6          // flag margin (iou units); worst-case f32 err <= 1.1e-6
#define FLAG_CAP (1 << 16)

// ---------------- scratch (static device memory) ----------------------------
__device__ __align__(16) float  g_Pf[2][NDET][HW];      // sorted probs (f32)
__device__ double        g_ud[2][NDET];                 // sorted row sums (f64)
__device__ __align__(16) float g_partial[2][2][NDET][NDET]; // [side][khalf] Gram partials
__device__ __align__(16) unsigned int g_bits[2][NDET][16];  // packed mask rows
__device__ unsigned char g_sup[2][NDET];
__device__ int           g_order[NDET];
__device__ int           g_rank[NDET];
__device__ int           g_nflag;
__device__ int           g_flags[FLAG_CAP];             // (side<<20)|(i<<10)|j

// ---------------- 1. stable argsort(-scores) --------------------------------
__global__ void order_kernel(const float* __restrict__ scores) {
    int i = threadIdx.x;
    float si = scores[i];
    int r = 0;
#pragma unroll 8
    for (int j = 0; j < NDET; ++j) {
        float sj = __ldg(&scores[j]);
        r += (sj > si) || (sj == si && j < i);
    }
    g_rank[i] = r;
    g_order[r] = i;
    if (i == 0) g_nflag = 0;
}

// ---------------- 2. gather channel, sigmoid, probs out + sorted f32 P ------
__global__ void prob_kernel(const float* __restrict__ left,
                            const float* __restrict__ right,
                            const int*   __restrict__ labels,
                            float*       __restrict__ out) {
    int b = blockIdx.x;
    int side = b >> 9;
    int n = b & (NDET - 1);
    const float* base = side ? right : left;
    int c = labels[n];
    const float* row = base + ((size_t)n * NC + c) * HW;
    float* orow = out + ((size_t)side * NDET + n) * HW;
    int r = g_rank[n];
    float* prow = g_Pf[side][r];

    double s = 0.0;
    for (int k = threadIdx.x; k < HW; k += blockDim.x) {
        float x = row[k];
        float p = 1.0f / (1.0f + expf(-x));
        orow[k] = p;
        prow[k] = p;
        s += (double)p;
    }
    __shared__ double red[8];
    for (int o = 16; o; o >>= 1) s += __shfl_down_sync(0xffffffffu, s, o);
    if ((threadIdx.x & 31) == 0) red[threadIdx.x >> 5] = s;
    __syncthreads();
    if (threadIdx.x == 0) {
        double t = 0.0;
#pragma unroll
        for (int w = 0; w < 8; ++w) t += red[w];
        g_ud[side][r] = t;
    }
}

// ---------------- 3. f32 Gram partials, Kahan acc, triangular, K-split ------
// grid (8,8,4): z = side*2 + khalf. BM=BN=64, BK=16, 4x4 micro-tile, all-f32.
__global__ void __launch_bounds__(256) gemm_partial_kernel() {
    if (blockIdx.x < blockIdx.y) return;   // upper triangle tiles only
    int side  = blockIdx.z >> 1;
    int khalf = blockIdx.z & 1;
    int kbeg = khalf ? 400 : 0;
    int kend = khalf ? HW  : 400;

    __shared__ __align__(16) float As[16][68];
    __shared__ __align__(16) float Bs[16][68];
    int tid = threadIdx.x;
    int tx = tid & 15, ty = tid >> 4;
    int arow0 = blockIdx.y * 64;
    int brow0 = blockIdx.x * 64;
    const float* P = &g_Pf[side][0][0];

    float s[4][4], c[4][4];
#pragma unroll
    for (int m = 0; m < 4; ++m)
#pragma unroll
        for (int n = 0; n < 4; ++n) { s[m][n] = 0.0f; c[m][n] = 0.0f; }

    int rr = tid >> 2, kq = (tid & 3) * 4;
    for (int kt = kbeg; kt < kend; kt += 16) {
        float4 av = *(const float4*)&P[(size_t)(arow0 + rr) * HW + kt + kq];
        float4 bv = *(const float4*)&P[(size_t)(brow0 + rr) * HW + kt + kq];
        As[kq + 0][rr] = av.x; As[kq + 1][rr] = av.y;
        As[kq + 2][rr] = av.z; As[kq + 3][rr] = av.w;
        Bs[kq + 0][rr] = bv.x; Bs[kq + 1][rr] = bv.y;
        Bs[kq + 2][rr] = bv.z; Bs[kq + 3][rr] = bv.w;
        __syncthreads();
        float tacc[4][4];
#pragma unroll
        for (int m = 0; m < 4; ++m)
#pragma unroll
            for (int n = 0; n < 4; ++n) tacc[m][n] = 0.0f;
#pragma unroll
        for (int kk = 0; kk < 16; ++kk) {
            float4 a4 = *(const float4*)&As[kk][ty * 4];
            float4 b4 = *(const float4*)&Bs[kk][tx * 4];
            float a[4] = {a4.x, a4.y, a4.z, a4.w};
            float bb[4] = {b4.x, b4.y, b4.z, b4.w};
#pragma unroll
            for (int m = 0; m < 4; ++m)
#pragma unroll
                for (int n = 0; n < 4; ++n) tacc[m][n] = fmaf(a[m], bb[n], tacc[m][n]);
        }
        // Kahan add of the tile partial (exact-rounded adds; no reassociation)
#pragma unroll
        for (int m = 0; m < 4; ++m)
#pragma unroll
            for (int n = 0; n < 4; ++n) {
                float y = __fadd_rn(tacc[m][n], -c[m][n]);
                float t = __fadd_rn(s[m][n], y);
                c[m][n] = __fadd_rn(__fadd_rn(t, -s[m][n]), -y);
                s[m][n] = t;
            }
        __syncthreads();
    }

    float* dst = &g_partial[side][khalf][0][0];
#pragma unroll
    for (int m = 0; m < 4; ++m) {
        int gi = arow0 + ty * 4 + m;
        float4 v = make_float4(s[m][0], s[m][1], s[m][2], s[m][3]);
        *(float4*)&dst[(size_t)gi * NDET + brow0 + tx * 4] = v;
    }
}

// ---------------- 3b. combine halves (f64), threshold, pack bits, flags -----
// grid (NDET, 2), 512 threads: one block per (row, side).
__global__ void epilogue_kernel() {
    int i = blockIdx.x;
    int side = blockIdx.y;
    int j = threadIdx.x;
    double den = g_ud[side][i] + EPSV;
    float p0 = g_partial[side][0][i][j];
    float p1 = g_partial[side][1][i][j];
    double inter = (double)p0 + (double)p1;
    double mg = inter - 0.5 * den;
    bool bit = (mg >= 0.0);
    // only upper triangle (j > i) feeds NMS; flag near-threshold pairs there
    if (j > i && fabs(mg) <= TAU * den) {
        int idx = atomicAdd(&g_nflag, 1);
        if (idx < FLAG_CAP)
            g_flags[idx] = (side << 20) | (i << 10) | j;
    }
    unsigned int w = __ballot_sync(0xffffffffu, bit);
    if ((j & 31) == 0) g_bits[side][i][j >> 5] = w;
}

// ---------------- 3c. exact f64 refinement of near-threshold pairs ----------
__global__ void refine_kernel() {
    int lane = threadIdx.x & 31;
    int warp = (blockIdx.x * blockDim.x + threadIdx.x) >> 5;
    int nwarps = (gridDim.x * blockDim.x) >> 5;
    int n = g_nflag;
    if (n > FLAG_CAP) n = FLAG_CAP;
    for (int p = warp; p < n; p += nwarps) {
        int v = g_flags[p];
        int side = v >> 20, i = (v >> 10) & 1023, j = v & 1023;
        const float* Pi = g_Pf[side][i];
        const float* Pj = g_Pf[side][j];
        double sum = 0.0;
#pragma unroll
        for (int q = 0; q < 25; ++q) {
            int k = lane + q * 32;
            float a = (k < HW) ? Pi[k] : 0.0f;
            float b = (k < HW) ? Pj[k] : 0.0f;
            sum = fma((double)a, (double)b, sum);
        }
        for (int o = 16; o; o >>= 1) sum += __shfl_down_sync(0xffffffffu, sum, o);
        if (lane == 0) {
            double den = g_ud[side][i] + EPSV;
            unsigned int bit = 1u << (j & 31);
            unsigned int* w = &g_bits[side][i][j >> 5];
            if (sum / den >= NMS_THRESH) atomicOr(w, bit);
            else                         atomicAnd(w, ~bit);
        }
    }
}

// ---------------- 4. greedy suppression: iterate kept rows only -------------
__global__ void nms_kernel() {
    int side = blockIdx.x;
    __shared__ unsigned int rb[NDET * 16];
    int lane = threadIdx.x;  // 32 threads
    const uint4* src = (const uint4*)&g_bits[side][0][0];
    for (int q = lane; q < NDET * 4; q += 32) ((uint4*)rb)[q] = src[q];
    __syncwarp();

    unsigned int removed = 0;  // lane w<16 holds suppression word w
    int i = 0;                 // row 0 is always kept
    while (true) {
        int rw = i >> 5, rbit = i & 31;
        unsigned int hi = (rbit == 31) ? 0u : (0xFFFFFFFFu << (rbit + 1));
        // OR row i's suppression set (only bits j > i)
        unsigned int m = (lane < 16) ? rb[i * 16 + lane] : 0u;
        if (lane < rw) m = 0u;
        else if (lane == rw) m &= hi;
        removed |= m;
        // next kept row: first clear bit of removed strictly above i
        unsigned int cand = (lane < 16) ? ~removed : 0u;
        if (lane < rw) cand = 0u;
        else if (lane == rw) cand &= hi;
        unsigned int ball = __ballot_sync(0xffffffffu, cand != 0u);
        if (!ball) break;
        int w = __ffs(ball) - 1;
        unsigned int word = __shfl_sync(0xffffffffu, cand, w);
        i = w * 32 + __ffs(word) - 1;
    }
    if (lane < 16) {
#pragma unroll
        for (int b = 0; b < 32; ++b)
            g_sup[side][lane * 32 + b] = (removed >> b) & 1u;
    }
}

// ---------------- 5. keep[order[r]] = valid & !supL & !supR -----------------
__global__ void finalize_kernel(float* __restrict__ out, int out_size) {
    int r = threadIdx.x;
    int n = g_order[r];
    bool valid = (g_ud[0][r] > 0.0) && (g_ud[1][r] > 0.0);
    float k = (valid && !g_sup[0][r] && !g_sup[1][r]) ? 1.0f : 0.0f;
    if (out_size >= 2 * NDET * HW + NDET)
        out[2 * NDET * HW + n] = k;
}

// ---------------- launch -----------------------------------------------------
extern "C" void kernel_launch(void* const* d_in, const int* in_sizes, int n_in,
                              void* d_out, int out_size) {
    const float* left   = (const float*)d_in[0];
    const float* right  = (const float*)d_in[1];
    const float* scores = (const float*)d_in[2];
    const int*   labels = (const int*)d_in[3];
    float* out = (float*)d_out;
    (void)in_sizes; (void)n_in;

    order_kernel<<<1, NDET>>>(scores);
    prob_kernel<<<2 * NDET, 256>>>(left, right, labels, out);
    dim3 ggrid(8, 8, 4);
    gemm_partial_kernel<<<ggrid, 256>>>();
    dim3 egrid(NDET, 2);
    epilogue_kernel<<<egrid, NDET>>>();
    refine_kernel<<<64, 256>>>();
    nms_kernel<<<2, 32>>>();
    finalize_kernel<<<1, NDET>>>(out, out_size);
}